// round 1
// baseline (speedup 1.0000x reference)
#include <cuda_runtime.h>

// LBP (radius=1, 8 points, skimage 'default') over NCHW fp32, zero boundary.
//
// Per pixel: 4 cardinal neighbors are exact integer samples (reference's
// rounded offsets make fr=fc=0 there); 4 diagonals are bilinear with
// F=0.70710678, G=1-F, accumulated in the reference's win(0,0),win(0,1),
// win(1,0),win(1,1) order per quadrant.

#define TW 128
#define TH 16
#define PW (TW + 2)   // 130
#define PH (TH + 2)   // 18

__global__ __launch_bounds__(512) void lbp_kernel(
    const float* __restrict__ in, float* __restrict__ out)
{
    constexpr int H = 224, W = 224;
    __shared__ float s[PH][PW];

    const int plane = blockIdx.z;
    const float* ip = in + (size_t)plane * (H * W);
    float*       op = out + (size_t)plane * (H * W);

    const int gx0 = blockIdx.x * TW;
    const int gy0 = blockIdx.y * TH;
    const int tid = threadIdx.y * 128 + threadIdx.x;

    // Cooperative halo load: 18*130 = 2340 elems, 512 threads -> 5 iters.
    #pragma unroll
    for (int i = tid; i < PH * PW; i += 512) {
        const int ly = i / PW;
        const int lx = i - ly * PW;
        const int gy = gy0 + ly - 1;
        const int gx = gx0 + lx - 1;
        float v = 0.0f;
        if ((unsigned)gy < (unsigned)H && (unsigned)gx < (unsigned)W)
            v = __ldg(ip + gy * W + gx);
        s[ly][lx] = v;
    }
    __syncthreads();

    const int lx = threadIdx.x;      // column within tile (stride-1 per warp: conflict-free LDS)
    const int x  = gx0 + lx;
    if (x >= W) return;
    const int ly0 = threadIdx.y * 4; // this thread handles 4 consecutive rows

    // Load 6 rows x 3 cols from smem into registers.
    float a[6][3];
    #pragma unroll
    for (int r = 0; r < 6; r++) {
        #pragma unroll
        for (int k = 0; k < 3; k++)
            a[r][k] = s[ly0 + r][lx + k];
    }

    // Bilinear weights, computed in double then cast (matches jax scalar math).
    const double Fd = 0.70710678;
    const double Gd = 1.0 - Fd;
    const float WD = (float)(Fd * Fd);   // far diagonal corner
    const float WE = (float)(Fd * Gd);   // adjacent edge neighbors
    const float WC = (float)(Gd * Gd);   // center contribution

    #pragma unroll
    for (int r = 0; r < 4; r++) {
        const float nw = a[r][0],     nn = a[r][1],     ne = a[r][2];
        const float ww = a[r + 1][0], c  = a[r + 1][1], ee = a[r + 1][2];
        const float sw = a[r + 2][0], ss = a[r + 2][1], se = a[r + 2][2];

        // Diagonal bilinear samples, reference accumulation order:
        // p=1 (up-right):   w00@N, w01@NE, w10@C, w11@E
        const float v1 = ((WE * nn + WD * ne) + WC * c) + WE * ee;
        // p=3 (up-left):    w00@NW, w01@N, w10@W, w11@C
        const float v3 = ((WD * nw + WE * nn) + WE * ww) + WC * c;
        // p=5 (down-left):  w00@W, w01@C, w10@SW, w11@S
        const float v5 = ((WE * ww + WC * c) + WD * sw) + WE * ss;
        // p=7 (down-right): w00@C, w01@E, w10@S, w11@SE
        const float v7 = ((WC * c + WE * ee) + WE * ss) + WD * se;

        float code = 0.0f;
        code += (ee >= c) ?   1.0f : 0.0f;  // p=0: east
        code += (v1 >= c) ?   2.0f : 0.0f;  // p=1
        code += (nn >= c) ?   4.0f : 0.0f;  // p=2: north
        code += (v3 >= c) ?   8.0f : 0.0f;  // p=3
        code += (ww >= c) ?  16.0f : 0.0f;  // p=4: west
        code += (v5 >= c) ?  32.0f : 0.0f;  // p=5
        code += (ss >= c) ?  64.0f : 0.0f;  // p=6: south
        code += (v7 >= c) ? 128.0f : 0.0f;  // p=7

        const int y = gy0 + ly0 + r;
        op[y * W + x] = code;
    }
}

extern "C" void kernel_launch(void* const* d_in, const int* in_sizes, int n_in,
                              void* d_out, int out_size)
{
    const float* x = (const float*)d_in[0];
    float* out = (float*)d_out;

    constexpr int H = 224, W = 224;
    const int planes = out_size / (H * W);   // B*C = 1024

    dim3 block(128, 4, 1);
    dim3 grid((W + TW - 1) / TW,             // 2
              (H + TH - 1) / TH,             // 14
              planes);                       // 1024
    lbp_kernel<<<grid, block>>>(x, out);
}

// round 2
// speedup vs baseline: 2.4339x; 2.4339x over previous
#include <cuda_runtime.h>

// LBP (radius=1, 8 points, skimage 'default') over NCHW fp32, zero boundary.
// Register-strip version: each thread owns a 4-wide x 8-tall output strip,
// keeping a rolling 3-row x 6-float register window. No shared memory, no
// __syncthreads, no per-load address IMADs in the hot loop.

__global__ __launch_bounds__(224) void lbp_kernel(
    const float* __restrict__ in, float* __restrict__ out)
{
    constexpr int H = 224, W = 224;

    const int plane = blockIdx.z;
    const float* ip = in + (size_t)plane * (H * W);
    float*       op = out + (size_t)plane * (H * W);

    const int g  = threadIdx.x;               // float4 column group 0..55
    const int x0 = g * 4;                     // column base
    const int y0 = blockIdx.y * 32 + threadIdx.y * 8;  // row base of 8-row strip

    const bool has_left  = (x0 > 0);
    const bool has_right = (x0 + 4 < W);

    // Bilinear weights (float32 of the double products, as jax produces).
    const double Fd = 0.70710678;
    const double Gd = 1.0 - Fd;
    const float WD = (float)(Fd * Fd);
    const float WE = (float)(Fd * Gd);
    const float WC = (float)(Gd * Gd);

    // Rolling 3-row window, 6 floats per row: [left, v0..v3, right]
    float buf[3][6];

    // Row loader: gy outside [0,H) -> zeros.
    auto load_row = [&](float* b, int gy) {
        if ((unsigned)gy < (unsigned)H) {
            const float* rp = ip + gy * W + x0;
            const float4 v = *reinterpret_cast<const float4*>(rp);
            b[0] = has_left  ? __ldg(rp - 1) : 0.0f;
            b[1] = v.x; b[2] = v.y; b[3] = v.z; b[4] = v.w;
            b[5] = has_right ? __ldg(rp + 4) : 0.0f;
        } else {
            b[0] = b[1] = b[2] = b[3] = b[4] = b[5] = 0.0f;
        }
    };

    load_row(buf[0], y0 - 1);
    load_row(buf[1], y0);

    #pragma unroll
    for (int r = 0; r < 8; r++) {
        load_row(buf[(r + 2) % 3], y0 + r + 1);

        const float* N = buf[r % 3];
        const float* C = buf[(r + 1) % 3];
        const float* S = buf[(r + 2) % 3];

        float4 res;
        float* resp = &res.x;

        #pragma unroll
        for (int i = 0; i < 4; i++) {
            const float nw = N[i], nn = N[i + 1], ne = N[i + 2];
            const float ww = C[i], c  = C[i + 1], ee = C[i + 2];
            const float sw = S[i], ss = S[i + 1], se = S[i + 2];

            // Diagonal bilinear samples; expressions identical to the
            // bit-exact round-1 kernel (same FMA contraction opportunities).
            const float v1 = ((WE * nn + WD * ne) + WC * c) + WE * ee; // up-right
            const float v3 = ((WD * nw + WE * nn) + WE * ww) + WC * c; // up-left
            const float v5 = ((WE * ww + WC * c) + WD * sw) + WE * ss; // down-left
            const float v7 = ((WC * c + WE * ee) + WE * ss) + WD * se; // down-right

            float code = (ee >= c) ? 1.0f : 0.0f;   // p=0: east
            if (v1 >= c) code += 2.0f;              // p=1
            if (nn >= c) code += 4.0f;              // p=2: north
            if (v3 >= c) code += 8.0f;              // p=3
            if (ww >= c) code += 16.0f;             // p=4: west
            if (v5 >= c) code += 32.0f;             // p=5
            if (ss >= c) code += 64.0f;             // p=6: south
            if (v7 >= c) code += 128.0f;            // p=7
            resp[i] = code;
        }

        *reinterpret_cast<float4*>(op + (y0 + r) * W + x0) = res;
    }
}

extern "C" void kernel_launch(void* const* d_in, const int* in_sizes, int n_in,
                              void* d_out, int out_size)
{
    const float* x = (const float*)d_in[0];
    float* out = (float*)d_out;

    constexpr int H = 224, W = 224;
    const int planes = out_size / (H * W);   // B*C = 1024

    dim3 block(56, 4, 1);                    // 224 threads: 56 col-groups x 4 strips
    dim3 grid(1, 7, planes);                 // 7 * 32 rows = 224
    lbp_kernel<<<grid, block>>>(x, out);
}